// round 6
// baseline (speedup 1.0000x reference)
#include <cuda_runtime.h>
#include <cstdint>

#define NBLK 152
#define TPB  512
#define B_N  4096
#define D_N  3072
#define C_N  10
#define MAXR 27
#define NW   (TPB / 32)
#define RPT  3
#define STG  4
#define TILE_FLOATS (RPT * D_N)
#define TILE_BYTES  (TILE_FLOATS * 4)
#define DYN_SMEM    (STG * TILE_BYTES)
#define R0BLK 23
#define REMROWS (B_N - R0BLK)
#define NB1 (NBLK - 1)

typedef unsigned long long ull;

__device__ float g_M[C_N * C_N];
__device__ float g_partial[NBLK];
__device__ unsigned int g_ticket;
__device__ unsigned int g_mflag;

__device__ __forceinline__ uint32_t smem_u32(const void* p) {
    uint32_t a;
    asm("{ .reg .u64 t; cvta.to.shared.u64 t, %1; cvt.u32.u64 %0, t; }" : "=r"(a) : "l"(p));
    return a;
}
__device__ __forceinline__ void mbar_init(uint32_t addr, uint32_t cnt) {
    asm volatile("mbarrier.init.shared.b64 [%0], %1;" :: "r"(addr), "r"(cnt) : "memory");
}
__device__ __forceinline__ void mbar_expect_tx(uint32_t addr, uint32_t bytes) {
    asm volatile("mbarrier.arrive.expect_tx.shared.b64 _, [%0], %1;" :: "r"(addr), "r"(bytes) : "memory");
}
__device__ __forceinline__ void bulk_g2s(uint32_t dst, const void* src, uint32_t bytes, uint32_t mbar) {
    asm volatile("cp.async.bulk.shared::cta.global.mbarrier::complete_tx::bytes [%0], [%1], %2, [%3];"
                 :: "r"(dst), "l"(src), "r"(bytes), "r"(mbar) : "memory");
}
__device__ __forceinline__ void mbar_wait(uint32_t addr, uint32_t parity) {
    uint32_t done;
    asm volatile(
        "{\n\t.reg .pred p;\n\t"
        "mbarrier.try_wait.parity.shared.b64 p, [%1], %2;\n\t"
        "selp.b32 %0, 1, 0, p;\n\t}"
        : "=r"(done) : "r"(addr), "r"(parity) : "memory");
    if (!done) {
        asm volatile(
            "{\n\t.reg .pred P1;\n\t"
            "WL_%=:\n\t"
            "mbarrier.try_wait.parity.shared.b64 P1, [%0], %1, 0x989680;\n\t"
            "@P1 bra.uni WD_%=;\n\t"
            "bra.uni WL_%=;\n\t"
            "WD_%=:\n\t}"
            :: "r"(addr), "r"(parity) : "memory");
    }
}

// One row: packed f32x2 FMA (X ull pairs straight from smem, no pack movs)
// + value-splitting warp reduction (17 SHFL).
__device__ __forceinline__ void do_row(const ull* __restrict__ row, int tid, int warp, int lane,
                                       const ull (&wp)[3][C_N],
                                       float (*sp)[NW][C_N], int r) {
    ull x0 = row[tid];
    ull x1 = row[tid + TPB];
    ull x2 = row[tid + 2 * TPB];
    ull acc[C_N];
#pragma unroll
    for (int k = 0; k < C_N; k++) acc[k] = 0ull;
#pragma unroll
    for (int k = 0; k < C_N; k++)
        asm("fma.rn.f32x2 %0, %1, %2, %0;" : "+l"(acc[k]) : "l"(x0), "l"(wp[0][k]));
#pragma unroll
    for (int k = 0; k < C_N; k++)
        asm("fma.rn.f32x2 %0, %1, %2, %0;" : "+l"(acc[k]) : "l"(x1), "l"(wp[1][k]));
#pragma unroll
    for (int k = 0; k < C_N; k++)
        asm("fma.rn.f32x2 %0, %1, %2, %0;" : "+l"(acc[k]) : "l"(x2), "l"(wp[2][k]));

    float z[C_N];
#pragma unroll
    for (int k = 0; k < C_N; k++) {
        float lo, hi;
        asm("mov.b64 {%0, %1}, %2;" : "=f"(lo), "=f"(hi) : "l"(acc[k]));
        z[k] = lo + hi;
    }

    // Value-splitting reduction: 10 -> 5 (xor16), 5 -> 3 (xor8), then 3x3 naive
    const bool hi16 = (lane & 16) != 0;
    const bool hi8  = (lane & 8) != 0;
    float v[5];
#pragma unroll
    for (int j = 0; j < 5; j++) {
        float send = hi16 ? z[j] : z[j + 5];
        float oth = __shfl_xor_sync(0xffffffffu, send, 16);
        v[j] = (hi16 ? z[j + 5] : z[j]) + oth;
    }
    float u[3];
#pragma unroll
    for (int j = 0; j < 3; j++) {
        float mine = (j < 2) ? v[j + 3] : 0.f;
        float send = hi8 ? v[j] : mine;
        float oth = __shfl_xor_sync(0xffffffffu, send, 8);
        u[j] = (hi8 ? mine : v[j]) + oth;
    }
#pragma unroll
    for (int off = 4; off; off >>= 1)
#pragma unroll
        for (int j = 0; j < 3; j++)
            u[j] += __shfl_xor_sync(0xffffffffu, u[j], off);

    if ((lane & 7) == 0) {
        int vb = (hi16 ? 5 : 0) + (hi8 ? 3 : 0);
        int c = hi8 ? 2 : 3;
#pragma unroll
        for (int j = 0; j < 3; j++)
            if (j < c) sp[r][warp][vb + j] = u[j];
    }
}

__global__ void __launch_bounds__(TPB, 1) jacreg_kernel(
        const float* __restrict__ X, const float* __restrict__ W,
        float* __restrict__ out) {
    extern __shared__ float tiles[];
    __shared__ float sM[C_N * C_N];
    __shared__ float sp[MAXR][NW][C_N];
    __shared__ float redM[NW][56];
    __shared__ ull mbar[STG];
    __shared__ int slast;

    const int tid = threadIdx.x, b = blockIdx.x;
    const int warp = tid >> 5, lane = tid & 31;
    int r0, r1;
    if (b == 0) { r0 = 0; r1 = R0BLK; }
    else {
        r0 = R0BLK + (int)(((long long)(b - 1) * REMROWS) / NB1);
        r1 = R0BLK + (int)(((long long)b * REMROWS) / NB1);
    }
    const int nrows = r1 - r0;
    const int ntiles = (nrows + RPT - 1) / RPT;

    // W packed as adjacent-d pairs: wp[j][k] = (W[e][k], W[e+1][k]), e = (j*TPB+tid)*2
    ull wp[3][C_N];
#pragma unroll
    for (int j = 0; j < 3; j++) {
        int e = (j * TPB + tid) * 2;
        const float* w0 = W + (size_t)e * C_N;
        const float* w1 = w0 + C_N;
#pragma unroll
        for (int k = 0; k < C_N; k++) {
            float a = __ldg(w0 + k), bb = __ldg(w1 + k);
            asm("mov.b64 %0, {%1, %2};" : "=l"(wp[j][k]) : "f"(a), "f"(bb));
        }
    }

    uint32_t mbar_a = smem_u32(&mbar[0]);
    uint32_t tile_a = smem_u32(&tiles[0]);

    if (tid == 0) {
#pragma unroll
        for (int s = 0; s < STG; s++) mbar_init(mbar_a + 8 * s, 1);
        asm volatile("fence.proxy.async.shared::cta;" ::: "memory");
    }
    __syncthreads();

    // Prologue: fill stages (overlaps block0's M computation)
    if (tid == 0) {
        int np = (ntiles < STG) ? ntiles : STG;
        for (int t = 0; t < np; t++) {
            int rbase = t * RPT;
            int cnt = nrows - rbase; if (cnt > RPT) cnt = RPT;
            uint32_t bytes = (uint32_t)cnt * D_N * 4;
            mbar_expect_tx(mbar_a + 8 * t, bytes);
            bulk_g2s(tile_a + t * TILE_BYTES,
                     X + (size_t)(r0 + rbase) * D_N, bytes, mbar_a + 8 * t);
        }
    }

    // Block 0: M = W^T W from wp registers; publish with release flag
    if (b == 0) {
        float w[6][C_N];
#pragma unroll
        for (int j = 0; j < 3; j++)
#pragma unroll
            for (int k = 0; k < C_N; k++)
                asm("mov.b64 {%0, %1}, %2;"
                    : "=f"(w[2 * j][k]), "=f"(w[2 * j + 1][k]) : "l"(wp[j][k]));
        int idx = 0;
#pragma unroll
        for (int k = 0; k < C_N; k++) {
            float a[C_N];
#pragma unroll
            for (int l = k; l < C_N; l++) {
                float s = 0.f;
#pragma unroll
                for (int pos = 0; pos < 6; pos++) s += w[pos][k] * w[pos][l];
                a[l - k] = s;
            }
#pragma unroll
            for (int off = 16; off; off >>= 1)
#pragma unroll
                for (int t = 0; t < C_N - k; t++)
                    a[t] += __shfl_xor_sync(0xffffffffu, a[t], off);
            if (lane == 0)
#pragma unroll
                for (int t = 0; t < C_N - k; t++) redM[warp][idx + t] = a[t];
            idx += C_N - k;
        }
        __syncthreads();
        if (tid < 55) {
            float s = 0.f;
#pragma unroll
            for (int wv = 0; wv < NW; wv++) s += redM[wv][tid];
            int k = 0, t = tid;
            while (t >= C_N - k) { t -= C_N - k; k++; }
            int l = k + t;
            g_M[k * C_N + l] = s;
            g_M[l * C_N + k] = s;
        }
        __syncthreads();
        if (tid == 0) {
            __threadfence();
            *(volatile unsigned int*)&g_mflag = 1u;
        }
    }

    // -------- Phase A: paired tiles (one barrier per 2 tiles) --------
    for (int t = 0; t < ntiles; t += 2) {
        {
            int s = t & (STG - 1);
            mbar_wait(mbar_a + 8 * s, (t / STG) & 1);
            int rbase = t * RPT;
            int cnt = nrows - rbase; if (cnt > RPT) cnt = RPT;
            const ull* tile = (const ull*)(tiles + s * TILE_FLOATS);
            for (int rl = 0; rl < cnt; rl++)
                do_row(tile + rl * (D_N / 2), tid, warp, lane, wp, sp, rbase + rl);
        }
        if (t + 1 < ntiles) {
            int s = (t + 1) & (STG - 1);
            mbar_wait(mbar_a + 8 * s, ((t + 1) / STG) & 1);
            int rbase = (t + 1) * RPT;
            int cnt = nrows - rbase; if (cnt > RPT) cnt = RPT;
            const ull* tile = (const ull*)(tiles + s * TILE_FLOATS);
            for (int rl = 0; rl < cnt; rl++)
                do_row(tile + rl * (D_N / 2), tid, warp, lane, wp, sp, rbase + rl);
        }
        __syncthreads();   // reads of both stages done
        if (tid == 0) {
#pragma unroll
            for (int d = 0; d < 2; d++) {
                int tt = t + STG + d;
                if (tt < ntiles) {
                    int rb = tt * RPT;
                    int c = nrows - rb; if (c > RPT) c = RPT;
                    uint32_t bytes = (uint32_t)c * D_N * 4;
                    int s = tt & (STG - 1);
                    mbar_expect_tx(mbar_a + 8 * s, bytes);
                    bulk_g2s(tile_a + s * TILE_BYTES,
                             X + (size_t)(r0 + rb) * D_N, bytes, mbar_a + 8 * s);
                }
            }
        }
    }

    // Acquire M (block0 published long ago)
    if (tid == 0) {
        volatile unsigned int* vf = &g_mflag;
        while (*vf == 0u) {}
        __threadfence();
    }
    __syncthreads();
    if (tid < C_N * C_N) sM[tid] = g_M[tid];
    __syncthreads();

    // -------- Phase B: one thread per row --------
    float myreg = 0.f;
    if (tid < nrows) {
        float z[C_N];
#pragma unroll
        for (int k = 0; k < C_N; k++) {
            float s = 0.f;
#pragma unroll
            for (int wv = 0; wv < NW; wv++) s += sp[tid][wv][k];
            z[k] = s;
        }
        float zmax = z[0];
#pragma unroll
        for (int k = 1; k < C_N; k++) zmax = fmaxf(zmax, z[k]);
        float q[C_N], qs = 0.f;
#pragma unroll
        for (int k = 0; k < C_N; k++) { q[k] = __expf(z[k] - zmax); qs += q[k]; }
        float inv = 1.f / qs;
#pragma unroll
        for (int k = 0; k < C_N; k++) q[k] *= inv;

        const float A = 1.0f - (float)C_N * 1e-6f;
        float p[C_N], sq[C_N];
#pragma unroll
        for (int k = 0; k < C_N; k++) { p[k] = q[k] * A + 1e-6f; sq[k] = sqrtf(p[k]); }
        float sm = sq[C_N - 1], qm = q[C_N - 1];
        float om = 1.f - sm;

        float uu[C_N], Qf = 0.f;
#pragma unroll
        for (int k = 0; k < C_N; k++) {
            float t = 0.f;
#pragma unroll
            for (int l = 0; l < C_N; l++) t += sM[k * C_N + l] * q[l];
            uu[k] = t;
            Qf += q[k] * t;
        }

        float jac2 = 0.f;
        float bfac = A * qm / (sm * om * om);
#pragma unroll
        for (int i = 0; i < C_N - 1; i++) {
            float al = A * q[i] / (sq[i] * om);
            float be = sq[i] * bfac;
            float ga = al + be;
            jac2 += al * al * sM[i * C_N + i]
                  + be * be * sM[C_N * C_N - 1]
                  + ga * ga * Qf
                  + 2.f * al * be * sM[i * C_N + (C_N - 1)]
                  - 2.f * al * ga * uu[i]
                  - 2.f * be * ga * uu[C_N - 1];
        }
        float jn = sqrtf(jac2);

        float ssum = 0.f;
#pragma unroll
        for (int k = 0; k < C_N; k++) ssum += sq[k];
        float arg = ssum * 0.316227766016838f;
        arg = fminf(fmaxf(arg, -1.f), 1.f);
        float delta = 2.f * acosf(arg);

        float psum = 0.f;
#pragma unroll
        for (int k = 0; k < C_N - 1; k++) psum += p[k];
        float rho = (2.f * om - psum) / om;

        float xv = jn - delta / (rho * 0.1f);
        myreg = (xv > 0.f) ? xv : expm1f(xv);
    }

    if (warp == 0) {
#pragma unroll
        for (int off = 16; off; off >>= 1)
            myreg += __shfl_xor_sync(0xffffffffu, myreg, off);
        if (lane == 0) {
            g_partial[b] = myreg;
            __threadfence();
            unsigned int rank = atomicAdd(&g_ticket, 1u);
            slast = (rank == NBLK - 1) ? 1 : 0;
            if (rank == NBLK - 1) {
                g_ticket = 0u;
                g_mflag = 0u;
            }
        }
    }
    __syncthreads();

    if (slast && warp == 0) {
        float s = 0.f;
        for (int i = lane; i < NBLK; i += 32) s += __ldcg(&g_partial[i]);
#pragma unroll
        for (int off = 16; off; off >>= 1)
            s += __shfl_xor_sync(0xffffffffu, s, off);
        if (lane == 0) out[0] = s * (1.f / (float)B_N);
    }
}

extern "C" void kernel_launch(void* const* d_in, const int* in_sizes, int n_in,
                              void* d_out, int out_size) {
    const float* X = (const float*)d_in[0];
    const float* W = (const float*)d_in[1];
    float* out = (float*)d_out;
    cudaFuncSetAttribute(jacreg_kernel,
                         cudaFuncAttributeMaxDynamicSharedMemorySize, DYN_SMEM);
    jacreg_kernel<<<NBLK, TPB, DYN_SMEM>>>(X, W, out);
}